// round 11
// baseline (speedup 1.0000x reference)
#include <cuda_runtime.h>
#include <math.h>

#define NB 32
#define NP 1024
#define NL 32
#define NH 128

__device__ float g_boxlT[NB*NH*NP];
__device__ float g_boxi [NB*NP*NH];
__device__ float g_text [NB*NL*NH];
__device__ float g_mask [NB*NP];
__device__ float g_cnt  [NB];
__device__ float g_tgt  [NB*NL*NP];
__device__ float g_nl   [NB*NL];
__device__ float g_lse  [NB*NP];
__device__ float g_lang [NB*NL];
__device__ float g_iou  [NB*NL];
__device__ int      g_idx [NB*NP];
__device__ int      g_pos [NB*NP];
__device__ int      g_cntI[NB];
__device__ int      g_nli [NB*NL];
__device__ int      g_plist[NB*NL*NP];
__device__ unsigned g_boxc[NB*NP*NH];   // compacted, tf32 bits

// ---------------- mask + prefix-scan compaction (merged) ----------------
__global__ __launch_bounds__(1024) void k_maskscan(const float* __restrict__ obj) {
    int b = blockIdx.x, tid = threadIdx.x, lane = tid&31, w = tid>>5;
    __shared__ int wc[32], wo[32];
    float s0 = obj[(b*NP+tid)*2], s1 = obj[(b*NP+tid)*2+1];
    int m = (s1 > s0);
    g_mask[b*NP+tid] = m ? 1.f : 0.f;
    unsigned bal = __ballot_sync(~0u, m);
    int before = __popc(bal & ((1u<<lane)-1u));
    if (lane==0) wc[w] = __popc(bal);
    __syncthreads();
    if (tid < 32) {
        int v = wc[tid];
        #pragma unroll
        for (int o=1;o<32;o<<=1){ int t=__shfl_up_sync(~0u,v,o); if (lane>=o) v+=t; }
        wo[tid] = v - wc[tid];
        if (tid==31) { g_cntI[b] = v; g_cnt[b] = (float)v; }
    }
    __syncthreads();
    int pos = wo[w] + before;
    g_pos[b*NP+tid] = pos;
    if (m) g_idx[b*NP+pos] = tid;
    __syncthreads();
    int cnt = g_cntI[b];
    int padded = (cnt + 127) & ~127;
    for (int e = cnt*NH + tid; e < padded*NH; e += 1024)
        g_boxc[b*NP*NH + e] = 0u;
}

// ---------------- targets + per-(b,l) positive index lists ----------------
__global__ __launch_bounds__(256) void k_tgt(const float* __restrict__ pc, const float* __restrict__ ps,
                      const float* __restrict__ gc, const float* __restrict__ gs) {
    int l = blockIdx.x, b = blockIdx.y, tid = threadIdx.x;
    int lane = tid & 31, w = tid >> 5;
    __shared__ float sg[6];
    __shared__ int wcnt[8], base_s;
    if (tid < 3) { sg[tid] = gc[(b*NL+l)*3+tid]; sg[3+tid] = gs[(b*NL+l)*3+tid] + 0.01f; }
    if (tid == 0) base_s = 0;
    __syncthreads();
    float gl[3], gh[3], volg = sg[3]*sg[4]*sg[5];
    #pragma unroll
    for (int d=0; d<3; d++) { gl[d]=sg[d]-0.5f*sg[3+d]; gh[d]=sg[d]+0.5f*sg[3+d]; }
    int* plist = g_plist + (b*NL+l)*NP;
    for (int c = 0; c < 4; c++) {
        int p = c*256 + tid, base = (b*NP+p)*3;
        float inter = 1.f, volp = 1.f;
        #pragma unroll
        for (int d=0; d<3; d++) {
            float cc = pc[base+d], ss = ps[base+d];
            float lo = fmaxf(gl[d], cc-ss*0.5f), hi = fminf(gh[d], cc+ss*0.5f);
            inter *= fmaxf(hi-lo, 0.f); volp *= ss;
        }
        float iou = inter / (volg + volp - inter + 1e-7f);
        float t = (iou > 0.25f) ? g_mask[b*NP+p] : 0.f;
        g_tgt[(b*NL+l)*NP+p] = t;
        unsigned bal = __ballot_sync(~0u, t > 0.f);
        if (lane == 0) wcnt[w] = __popc(bal);
        __syncthreads();
        if (tid == 0) {
            int s = base_s;
            for (int ww = 0; ww < 8; ww++) { int cc = wcnt[ww]; wcnt[ww] = s; s += cc; }
            base_s = s;
        }
        __syncthreads();
        if (t > 0.f) plist[wcnt[w] + __popc(bal & ((1u<<lane)-1u))] = p;
        __syncthreads();
    }
    if (tid == 0) { g_nl[b*NL+l] = (float)base_s; g_nli[b*NL+l] = base_s; }
}

__device__ __forceinline__ unsigned f2tf(float f) {
    unsigned u; asm("cvt.rna.tf32.f32 %0, %1;" : "=r"(u) : "f"(f)); return u;
}
__device__ __forceinline__ uint4 f2tf4(float4 v) {
    return make_uint4(f2tf(v.x), f2tf(v.y), f2tf(v.z), f2tf(v.w));
}
__device__ __forceinline__ void mma_tf32(float* c, const unsigned* a, const unsigned* bb) {
    asm volatile("mma.sync.aligned.m16n8k8.row.col.f32.tf32.tf32.f32 "
                 "{%0,%1,%2,%3}, {%4,%5,%6,%7}, {%8,%9}, {%0,%1,%2,%3};"
                 : "+f"(c[0]), "+f"(c[1]), "+f"(c[2]), "+f"(c[3])
                 : "r"(a[0]), "r"(a[1]), "r"(a[2]), "r"(a[3]), "r"(bb[0]), "r"(bb[1]));
}

// ---------------- k_text: tf32 TC, 128 rows/block ----------------
#define TEXT_SMEM (2*128*132*4)
__global__ __launch_bounds__(256) void k_text_tc(const float* __restrict__ emb,
                                                 const float* __restrict__ Wt) {
    extern __shared__ unsigned su[];
    unsigned* av = su;               // [128][132] emb rows
    unsigned* wt = su + 128*132;     // [128][132] Wt[h][k]
    const int r0 = blockIdx.x*128, tid = threadIdx.x;
    const float4* e4 = (const float4*)(emb + r0*NH);
    const float4* w4 = (const float4*)Wt;
    for (int idx = tid; idx < 4096; idx += 256) {
        int r = idx >> 5, k4 = idx & 31;
        *(uint4*)&av[r*132 + k4*4] = f2tf4(e4[idx]);
        *(uint4*)&wt[r*132 + k4*4] = f2tf4(w4[idx]);
    }
    __syncthreads();
    const int wid = tid>>5, lane = tid&31, g = lane>>2, t4 = lane&3;
    float acc[16][4];
    #pragma unroll
    for (int nf=0;nf<16;nf++)
        #pragma unroll
        for (int i=0;i<4;i++) acc[nf][i]=0.f;
    #pragma unroll
    for (int ks = 0; ks < 16; ks++) {
        const int k0 = ks*8;
        unsigned af[4];
        int base = (wid*16 + g)*132 + k0 + t4;
        af[0] = av[base]; af[1] = av[base + 8*132];
        af[2] = av[base + 4]; af[3] = av[base + 8*132 + 4];
        #pragma unroll
        for (int nf = 0; nf < 16; nf++) {
            int bb = (nf*8 + g)*132 + k0 + t4;
            unsigned bf[2] = { wt[bb], wt[bb + 4] };
            mma_tf32(acc[nf], af, bf);
        }
    }
    float sA = 0.f, sB = 0.f;
    #pragma unroll
    for (int nf = 0; nf < 16; nf++) {
        sA += acc[nf][0]*acc[nf][0] + acc[nf][1]*acc[nf][1];
        sB += acc[nf][2]*acc[nf][2] + acc[nf][3]*acc[nf][3];
    }
    #pragma unroll
    for (int o = 1; o < 4; o <<= 1) {
        sA += __shfl_xor_sync(~0u, sA, o);
        sB += __shfl_xor_sync(~0u, sB, o);
    }
    float iA = 1.f/fmaxf(sqrtf(sA), 1e-12f);
    float iB = 1.f/fmaxf(sqrtf(sB), 1e-12f);
    int rA = r0 + wid*16 + g, rB = rA + 8;
    #pragma unroll
    for (int nf = 0; nf < 16; nf++) {
        *(float2*)&g_text[rA*NH + nf*8 + t4*2] = make_float2(acc[nf][0]*iA, acc[nf][1]*iA);
        *(float2*)&g_text[rB*NH + nf*8 + t4*2] = make_float2(acc[nf][2]*iB, acc[nf][3]*iB);
    }
}

// ---------------- k_proj: tf32 TC, 512 threads, 128 rows/block, both projections ----------------
#define PROJ_SMEM_B (3*128*132*4)
__global__ __launch_bounds__(512) void k_proj(const float* __restrict__ bbox,
                                              const float* __restrict__ Wp,
                                              const float* __restrict__ Wpi) {
    extern __shared__ unsigned su[];
    unsigned* av = su;                // [128][132] bbox rows (tf32)
    unsigned* wp = su + 128*132;      // [128][132] Wp[h][k]
    unsigned* wi = su + 2*128*132;    // [128][132] Wpi[h][k]
    const int m0 = blockIdx.x*128, b = m0 >> 10, p0 = m0 & 1023;
    const int tid = threadIdx.x;
    const float4* a4 = (const float4*)(bbox + m0*NH);
    const float4* p4 = (const float4*)Wp;
    const float4* i4 = (const float4*)Wpi;
    for (int idx = tid; idx < 4096; idx += 512) {
        int r = idx >> 5, k4 = idx & 31;
        *(uint4*)&av[r*132 + k4*4] = f2tf4(a4[idx]);
        *(uint4*)&wp[r*132 + k4*4] = f2tf4(p4[idx]);
        *(uint4*)&wi[r*132 + k4*4] = f2tf4(i4[idx]);
    }
    __syncthreads();
    const int wid = tid>>5, lane = tid&31, g = lane>>2, t4 = lane&3;
    const int wm = wid & 7, wn = wid >> 3;     // wn: 0 -> Wp(boxl), 1 -> Wpi(boxi)
    const unsigned* wb = wn ? wi : wp;
    float acc[16][4];
    #pragma unroll
    for (int nf=0;nf<16;nf++)
        #pragma unroll
        for (int i=0;i<4;i++) acc[nf][i] = 0.f;

    #pragma unroll
    for (int ks = 0; ks < 16; ks++) {
        const int k0 = ks*8;
        unsigned af[4];
        int base = (wm*16 + g)*132 + k0 + t4;
        af[0] = av[base];
        af[1] = av[base + 8*132];
        af[2] = av[base + 4];
        af[3] = av[base + 8*132 + 4];
        #pragma unroll
        for (int nf = 0; nf < 16; nf++) {
            int bb = (nf*8 + g)*132 + k0 + t4;
            unsigned bf[2] = { wb[bb], wb[bb + 4] };
            mma_tf32(acc[nf], af, bf);
        }
    }
    // row-normalize: rows rA (c0,c1), rB (c2,c3); cols spread over t4-group
    float sA = 0.f, sB = 0.f;
    #pragma unroll
    for (int nf = 0; nf < 16; nf++) {
        sA += acc[nf][0]*acc[nf][0] + acc[nf][1]*acc[nf][1];
        sB += acc[nf][2]*acc[nf][2] + acc[nf][3]*acc[nf][3];
    }
    #pragma unroll
    for (int o = 1; o < 4; o <<= 1) {
        sA += __shfl_xor_sync(~0u, sA, o);
        sB += __shfl_xor_sync(~0u, sB, o);
    }
    float iA = 1.f/fmaxf(sqrtf(sA), 1e-12f);
    float iB = 1.f/fmaxf(sqrtf(sB), 1e-12f);
    #pragma unroll
    for (int nf = 0; nf < 16; nf++) {
        acc[nf][0] *= iA; acc[nf][1] *= iA;
        acc[nf][2] *= iB; acc[nf][3] *= iB;
    }
    const int rA = wm*16 + g, rB = rA + 8;
    if (wn == 1) {  // boxi: full fp32 layout + compacted tf32 rows
        #pragma unroll
        for (int rr = 0; rr < 2; rr++) {
            int rloc = rr ? rB : rA;
            int gp = m0 + rloc;
            float mk = g_mask[gp];
            int j = g_pos[gp];
            float* dst = g_boxi + gp*NH + t4*2;
            unsigned* cdst = (mk > 0.f) ? (g_boxc + (b*NP + j)*NH + t4*2) : 0;
            #pragma unroll
            for (int nf = 0; nf < 16; nf++) {
                float c0 = acc[nf][rr*2], c1 = acc[nf][rr*2+1];
                *(float2*)(dst + nf*8) = make_float2(c0, c1);
                if (cdst) {
                    uint2 u = make_uint2(f2tf(c0), f2tf(c1));
                    *(uint2*)(cdst + nf*8) = u;
                }
            }
        }
    }
    __syncthreads();
    float* ct = (float*)su;   // [128 h][132] transpose staging (reuses av region)
    if (wn == 0) {
        #pragma unroll
        for (int rr = 0; rr < 2; rr++) {
            int rloc = rr ? rB : rA;
            #pragma unroll
            for (int nf = 0; nf < 16; nf++) {
                ct[(nf*8 + t4*2    )*132 + rloc] = acc[nf][rr*2];
                ct[(nf*8 + t4*2 + 1)*132 + rloc] = acc[nf][rr*2+1];
            }
        }
    }
    __syncthreads();
    for (int idx = tid; idx < 128*128; idx += 512) {
        int h = idx >> 7, r = idx & 127;
        g_boxlT[(b*NH + h)*NP + p0 + r] = ct[h*132 + r];
    }
}

__device__ __forceinline__ int lang_num_at(const int* ln, int b) {
    return (ln[1] == 0) ? ln[2*b] : ln[b];
}

__global__ __launch_bounds__(256) void k_lang(const int* __restrict__ ln) {
    int b = blockIdx.y, l0 = blockIdx.x*8, tid = threadIdx.x;
    __shared__ float ts[8*NH];
    __shared__ float redm[8][8], reds[8][8], redt[8][8];
    for (int idx = tid; idx < 8*NH; idx += 256)
        ts[idx] = g_text[(b*NL + l0 + (idx>>7))*NH + (idx&127)];
    __syncthreads();
    float rm[8], rs[8], rt[8];
    #pragma unroll
    for (int j=0;j<8;j++) { rm[j]=-1e30f; rs[j]=0.f; rt[j]=0.f; }
    for (int c = 0; c < 4; c++) {
        int p = c*256 + tid;
        float acc[8];
        #pragma unroll
        for (int j=0;j<8;j++) acc[j]=0.f;
        const float* xT = g_boxlT + b*NH*NP + p;
        #pragma unroll 4
        for (int h = 0; h < 128; h++) {
            float bx = xT[h*NP];
            #pragma unroll
            for (int j=0;j<8;j++) acc[j] += bx * ts[j*NH + h];
        }
        float mv = g_mask[b*NP+p];
        #pragma unroll
        for (int j=0;j<8;j++) {
            rt[j] += g_tgt[(b*NL+l0+j)*NP + p] * acc[j];
            if (mv > 0.f) {
                float nm = fmaxf(rm[j], acc[j]);
                rs[j] = rs[j]*__expf(rm[j]-nm) + __expf(acc[j]-nm);
                rm[j] = nm;
            }
        }
    }
    int lane = tid & 31, w = tid >> 5;
    #pragma unroll
    for (int j=0;j<8;j++) {
        for (int o = 16; o; o >>= 1) {
            float om = __shfl_xor_sync(~0u, rm[j], o);
            float os = __shfl_xor_sync(~0u, rs[j], o);
            float nm = fmaxf(rm[j], om);
            rs[j] = rs[j]*__expf(rm[j]-nm) + os*__expf(om-nm);
            rm[j] = nm;
            rt[j] += __shfl_xor_sync(~0u, rt[j], o);
        }
        if (lane==0) { redm[w][j]=rm[j]; reds[w][j]=rs[j]; redt[w][j]=rt[j]; }
    }
    __syncthreads();
    if (tid < 8) {
        int j = tid;
        float m = redm[0][j], sa = reds[0][j], t = redt[0][j];
        for (int w2 = 1; w2 < 8; w2++) {
            float om = redm[w2][j], os = reds[w2][j];
            float nm = fmaxf(m, om);
            sa = sa*__expf(m-nm) + os*__expf(om-nm);
            m = nm; t += redt[w2][j];
        }
        float n = g_nl[b*NL+l0+j];
        float cnt1 = fmaxf(g_cnt[b], 1.f);
        float val = 0.f;
        if (n > 0.f) val = 0.5f*(n*(m + logf(sa)) - t)/cnt1;
        bool act = (l0+j) < lang_num_at(ln, b);
        g_lang[b*NL+l0+j] = act ? val : 0.f;
    }
}

// ---------------- k_iou: compacted tf32 TC GEMM + masked row logsumexp, 512 thr ----------------
#define IOU_TC_SMEM (2*128*132*4 + 128*4 + 2*2*128*4 + 2*128*4)
__global__ __launch_bounds__(512) void k_iou_tc() {
    extern __shared__ unsigned smu[];
    unsigned* as = smu;               // [128][132]
    unsigned* bs = smu + 128*132;     // [128][132]
    float* ms  = (float*)(smu + 2*128*132);
    float* pm  = ms + 128;
    float* ps  = pm + 256;
    float* rmS = ps + 256;
    float* rsS = rmS + 128;

    const int b = blockIdx.y, r0 = blockIdx.x*128, tid = threadIdx.x;
    const int cnt = g_cntI[b];
    if (r0 >= cnt) return;
    const int qtiles = (cnt + 127) >> 7;
    const int wid = tid >> 5, lane = tid & 31;
    const int g = lane >> 2, t4 = lane & 3;
    const int wm = wid & 7, wn = wid >> 3;
    const uint4* Xa = (const uint4*)(g_boxc + (b*NP + r0)*NH);

    for (int idx = tid; idx < 4096; idx += 512) {
        int r = idx >> 5, k4 = idx & 31;
        *(uint4*)&as[r*132 + k4*4] = Xa[idx];
    }
    if (tid < 128) { rmS[tid] = -1e30f; rsS[tid] = 0.f; }

    for (int qt = 0; qt < qtiles; qt++) {
        __syncthreads();
        const uint4* Xb = (const uint4*)(g_boxc + (b*NP + qt*128)*NH);
        for (int idx = tid; idx < 4096; idx += 512) {
            int q = idx >> 5, k4 = idx & 31;
            *(uint4*)&bs[q*132 + k4*4] = Xb[idx];
        }
        if (tid < 128) ms[tid] = (qt*128 + tid < cnt) ? 1.f : 0.f;
        __syncthreads();

        float acc[8][4];
        #pragma unroll
        for (int nf=0;nf<8;nf++)
            #pragma unroll
            for (int i=0;i<4;i++) acc[nf][i] = 0.f;

        #pragma unroll
        for (int ks = 0; ks < 16; ks++) {
            const int k0 = ks*8;
            unsigned af[4];
            int base = (wm*16 + g)*132 + k0 + t4;
            af[0] = as[base];
            af[1] = as[base + 8*132];
            af[2] = as[base + 4];
            af[3] = as[base + 8*132 + 4];
            #pragma unroll
            for (int nf = 0; nf < 8; nf++) {
                int bb = (wn*64 + nf*8 + g)*132 + k0 + t4;
                unsigned bf[2] = { bs[bb], bs[bb + 4] };
                mma_tf32(acc[nf], af, bf);
            }
        }
        float cm0[8], cm1[8];
        #pragma unroll
        for (int nf = 0; nf < 8; nf++) {
            cm0[nf] = ms[wn*64 + nf*8 + t4*2];
            cm1[nf] = ms[wn*64 + nf*8 + t4*2 + 1];
        }
        {
            const int rA = wm*16 + g, rB = rA + 8;
            float mA = -1e30f, mB = -1e30f;
            #pragma unroll
            for (int nf = 0; nf < 8; nf++) {
                mA = fmaxf(mA, (cm0[nf] > 0.f) ? acc[nf][0] : -1e30f);
                mA = fmaxf(mA, (cm1[nf] > 0.f) ? acc[nf][1] : -1e30f);
                mB = fmaxf(mB, (cm0[nf] > 0.f) ? acc[nf][2] : -1e30f);
                mB = fmaxf(mB, (cm1[nf] > 0.f) ? acc[nf][3] : -1e30f);
            }
            #pragma unroll
            for (int o = 1; o < 4; o <<= 1) {
                mA = fmaxf(mA, __shfl_xor_sync(~0u, mA, o));
                mB = fmaxf(mB, __shfl_xor_sync(~0u, mB, o));
            }
            float eA = 0.f, eB = 0.f;
            #pragma unroll
            for (int nf = 0; nf < 8; nf++) {
                eA += (cm0[nf] > 0.f) ? __expf(acc[nf][0] - mA) : 0.f;
                eA += (cm1[nf] > 0.f) ? __expf(acc[nf][1] - mA) : 0.f;
                eB += (cm0[nf] > 0.f) ? __expf(acc[nf][2] - mB) : 0.f;
                eB += (cm1[nf] > 0.f) ? __expf(acc[nf][3] - mB) : 0.f;
            }
            #pragma unroll
            for (int o = 1; o < 4; o <<= 1) {
                eA += __shfl_xor_sync(~0u, eA, o);
                eB += __shfl_xor_sync(~0u, eB, o);
            }
            if (t4 == 0) {
                pm[wn*128 + rA] = mA; ps[wn*128 + rA] = eA;
                pm[wn*128 + rB] = mB; ps[wn*128 + rB] = eB;
            }
        }
        __syncthreads();
        if (tid < 128) {
            float m0 = pm[tid], s0 = ps[tid], m1 = pm[128+tid], s1 = ps[128+tid];
            float tm = fmaxf(m0, m1);
            float te = ((s0 > 0.f) ? s0*__expf(m0 - tm) : 0.f)
                     + ((s1 > 0.f) ? s1*__expf(m1 - tm) : 0.f);
            float rm = rmS[tid], nm = fmaxf(rm, tm);
            float rs = rsS[tid];
            rs = ((rs > 0.f) ? rs*__expf(rm - nm) : 0.f)
               + ((te > 0.f) ? te*__expf(tm - nm) : 0.f);
            rmS[tid] = nm; rsS[tid] = rs;
        }
    }
    __syncthreads();
    if (tid < 128) {
        int r = r0 + tid;
        if (r < cnt) {
            float lse = (rsS[tid] > 0.f) ? rmS[tid] + logf(rsS[tid]) : 0.f;
            g_lse[b*NP + g_idx[b*NP + r]] = lse;
        }
    }
}

// ---------------- k_vsum: list-gather, exact fp32 ----------------
__global__ void k_vsum(const int* __restrict__ ln) {
    int l = blockIdx.x, b = blockIdx.y, h = threadIdx.x;  // 128
    int nn = g_nli[b*NL+l];
    const int* plist = g_plist + (b*NL+l)*NP;
    float v = 0.f;
    for (int j = 0; j < nn; j++) {
        int p = __ldg(&plist[j]);
        v += g_boxi[(b*NP + p)*NH + h];
    }
    float lsum = 0.f;
    for (int j = h; j < nn; j += 128)
        lsum += g_lse[b*NP + __ldg(&plist[j])];
    float vv = v*v;
    for (int o = 16; o; o >>= 1) {
        vv   += __shfl_xor_sync(~0u, vv, o);
        lsum += __shfl_xor_sync(~0u, lsum, o);
    }
    __shared__ float redv[4], redl[4];
    if ((h&31)==0) { redv[h>>5] = vv; redl[h>>5] = lsum; }
    __syncthreads();
    if (h == 0) {
        vv   = redv[0]+redv[1]+redv[2]+redv[3];
        lsum = redl[0]+redl[1]+redl[2]+redl[3];
        float n = g_nl[b*NL+l];
        float cnt1 = fmaxf(g_cnt[b], 1.f);
        float val = 0.f;
        if (n > 0.f) val = (n*lsum - vv)/(cnt1*cnt1);
        bool act = l < lang_num_at(ln, b);
        g_iou[b*NL+l] = act ? val : 0.f;
    }
}

__global__ void k_final(float* __restrict__ out) {
    int tid = threadIdx.x;  // 1024
    float a = g_lang[tid], c = g_iou[tid];
    for (int o = 16; o; o >>= 1) {
        a += __shfl_xor_sync(~0u, a, o);
        c += __shfl_xor_sync(~0u, c, o);
    }
    __shared__ float ra[32], rc[32];
    if ((tid&31)==0) { ra[tid>>5]=a; rc[tid>>5]=c; }
    __syncthreads();
    if (tid < 32) {
        a = ra[tid]; c = rc[tid];
        for (int o = 16; o; o >>= 1) {
            a += __shfl_xor_sync(~0u, a, o);
            c += __shfl_xor_sync(~0u, c, o);
        }
        if (tid == 0) { out[0] = a/(float)NB; out[1] = c/(float)NB; }
    }
}

extern "C" void kernel_launch(void* const* d_in, const int* in_sizes, int n_in,
                              void* d_out, int out_size) {
    const float* pred_center = (const float*)d_in[0];
    const float* pred_size   = (const float*)d_in[1];
    const float* bbox        = (const float*)d_in[2];
    const float* gt_center   = (const float*)d_in[3];
    const float* gt_size     = (const float*)d_in[4];
    const float* lang_emb    = (const float*)d_in[5];
    const float* obj         = (const float*)d_in[6];
    const float* Wt          = (const float*)d_in[7];
    const float* Wp          = (const float*)d_in[8];
    const float* Wpi         = (const float*)d_in[9];
    const int*   lang_num    = (const int*)d_in[10];
    float* out = (float*)d_out;

    static bool attr_done = false;
    if (!attr_done) {
        cudaFuncSetAttribute(k_proj, cudaFuncAttributeMaxDynamicSharedMemorySize,
                             PROJ_SMEM_B);
        cudaFuncSetAttribute(k_iou_tc, cudaFuncAttributeMaxDynamicSharedMemorySize,
                             IOU_TC_SMEM);
        cudaFuncSetAttribute(k_text_tc, cudaFuncAttributeMaxDynamicSharedMemorySize,
                             TEXT_SMEM);
        attr_done = true;
    }

    k_maskscan<<<NB, 1024>>>(obj);
    k_tgt<<<dim3(NL, NB), 256>>>(pred_center, pred_size, gt_center, gt_size);
    k_text_tc<<<(NB*NL)/128, 256, TEXT_SMEM>>>(lang_emb, Wt);
    k_proj<<<(NB*NP)/128, 512, PROJ_SMEM_B>>>(bbox, Wp, Wpi);
    k_iou_tc<<<dim3(NP/128, NB), 512, IOU_TC_SMEM>>>();
    k_lang<<<dim3(NL/8, NB), 256>>>(lang_num);
    k_vsum<<<dim3(NL, NB), 128>>>(lang_num);
    k_final<<<1, 1024>>>(out);
}

// round 12
// speedup vs baseline: 1.3862x; 1.3862x over previous
#include <cuda_runtime.h>
#include <math.h>

#define NB 32
#define NP 1024
#define NL 32
#define NH 128

__device__ float g_boxi [NB*NP*NH];
__device__ float g_text [NB*NL*NH];
__device__ float g_mask [NB*NP];
__device__ float g_cnt  [NB];
__device__ float g_tgtc [NB*NL*NP];     // targets in compacted column order
__device__ float g_nl   [NB*NL];
__device__ float g_lse  [NB*NP];
__device__ float g_lang [NB*NL];
__device__ float g_iou  [NB*NL];
__device__ int      g_idx [NB*NP];
__device__ int      g_pos [NB*NP];
__device__ int      g_cntI[NB];
__device__ int      g_nli [NB*NL];
__device__ int      g_plist[NB*NL*NP];
__device__ unsigned g_boxc [NB*NP*NH];  // compacted boxi, tf32 bits
__device__ unsigned g_boxlc[NB*NP*NH];  // compacted boxl, tf32 bits

// ---------------- mask + prefix-scan compaction ----------------
__global__ __launch_bounds__(1024) void k_maskscan(const float* __restrict__ obj) {
    int b = blockIdx.x, tid = threadIdx.x, lane = tid&31, w = tid>>5;
    __shared__ int wc[32], wo[32];
    float s0 = obj[(b*NP+tid)*2], s1 = obj[(b*NP+tid)*2+1];
    int m = (s1 > s0);
    g_mask[b*NP+tid] = m ? 1.f : 0.f;
    unsigned bal = __ballot_sync(~0u, m);
    int before = __popc(bal & ((1u<<lane)-1u));
    if (lane==0) wc[w] = __popc(bal);
    __syncthreads();
    if (tid < 32) {
        int v = wc[tid];
        #pragma unroll
        for (int o=1;o<32;o<<=1){ int t=__shfl_up_sync(~0u,v,o); if (lane>=o) v+=t; }
        wo[tid] = v - wc[tid];
        if (tid==31) { g_cntI[b] = v; g_cnt[b] = (float)v; }
    }
    __syncthreads();
    int pos = wo[w] + before;
    g_pos[b*NP+tid] = pos;
    if (m) g_idx[b*NP+pos] = tid;
    __syncthreads();
    int cnt = g_cntI[b];
    int padded = (cnt + 127) & ~127;
    for (int e = cnt*NH + tid; e < padded*NH; e += 1024) {
        g_boxc [b*NP*NH + e] = 0u;
        g_boxlc[b*NP*NH + e] = 0u;
    }
}

// ---------------- targets: compacted tgt rows + positive lists ----------------
__global__ __launch_bounds__(256) void k_tgt(const float* __restrict__ pc, const float* __restrict__ ps,
                      const float* __restrict__ gc, const float* __restrict__ gs) {
    int l = blockIdx.x, b = blockIdx.y, tid = threadIdx.x;
    int lane = tid & 31, w = tid >> 5;
    __shared__ float sg[6];
    __shared__ int wcnt[8], base_s;
    float* trow = g_tgtc + (b*NL+l)*NP;
    for (int i = tid; i < NP; i += 256) trow[i] = 0.f;
    if (tid < 3) { sg[tid] = gc[(b*NL+l)*3+tid]; sg[3+tid] = gs[(b*NL+l)*3+tid] + 0.01f; }
    if (tid == 0) base_s = 0;
    __syncthreads();
    float gl[3], gh[3], volg = sg[3]*sg[4]*sg[5];
    #pragma unroll
    for (int d=0; d<3; d++) { gl[d]=sg[d]-0.5f*sg[3+d]; gh[d]=sg[d]+0.5f*sg[3+d]; }
    int* plist = g_plist + (b*NL+l)*NP;
    for (int c = 0; c < 4; c++) {
        int p = c*256 + tid, base = (b*NP+p)*3;
        float inter = 1.f, volp = 1.f;
        #pragma unroll
        for (int d=0; d<3; d++) {
            float cc = pc[base+d], ss = ps[base+d];
            float lo = fmaxf(gl[d], cc-ss*0.5f), hi = fminf(gh[d], cc+ss*0.5f);
            inter *= fmaxf(hi-lo, 0.f); volp *= ss;
        }
        float iou = inter / (volg + volp - inter + 1e-7f);
        bool pos_t = (iou > 0.25f) && (g_mask[b*NP+p] > 0.f);
        if (pos_t) trow[g_pos[b*NP+p]] = 1.f;
        unsigned bal = __ballot_sync(~0u, pos_t);
        if (lane == 0) wcnt[w] = __popc(bal);
        __syncthreads();
        if (tid == 0) {
            int s = base_s;
            for (int ww = 0; ww < 8; ww++) { int cc = wcnt[ww]; wcnt[ww] = s; s += cc; }
            base_s = s;
        }
        __syncthreads();
        if (pos_t) plist[wcnt[w] + __popc(bal & ((1u<<lane)-1u))] = p;
        __syncthreads();
    }
    if (tid == 0) { g_nl[b*NL+l] = (float)base_s; g_nli[b*NL+l] = base_s; }
}

__device__ __forceinline__ unsigned f2tf(float f) {
    unsigned u; asm("cvt.rna.tf32.f32 %0, %1;" : "=r"(u) : "f"(f)); return u;
}
__device__ __forceinline__ uint4 f2tf4(float4 v) {
    return make_uint4(f2tf(v.x), f2tf(v.y), f2tf(v.z), f2tf(v.w));
}
__device__ __forceinline__ void mma_tf32(float* c, const unsigned* a, const unsigned* bb) {
    asm volatile("mma.sync.aligned.m16n8k8.row.col.f32.tf32.tf32.f32 "
                 "{%0,%1,%2,%3}, {%4,%5,%6,%7}, {%8,%9}, {%0,%1,%2,%3};"
                 : "+f"(c[0]), "+f"(c[1]), "+f"(c[2]), "+f"(c[3])
                 : "r"(a[0]), "r"(a[1]), "r"(a[2]), "r"(a[3]), "r"(bb[0]), "r"(bb[1]));
}

// ---------------- k_text: tf32 TC, 128 rows/block ----------------
#define TEXT_SMEM (2*128*132*4)
__global__ __launch_bounds__(256) void k_text_tc(const float* __restrict__ emb,
                                                 const float* __restrict__ Wt) {
    extern __shared__ unsigned su[];
    unsigned* av = su;
    unsigned* wt = su + 128*132;
    const int r0 = blockIdx.x*128, tid = threadIdx.x;
    const float4* e4 = (const float4*)(emb + r0*NH);
    const float4* w4 = (const float4*)Wt;
    for (int idx = tid; idx < 4096; idx += 256) {
        int r = idx >> 5, k4 = idx & 31;
        *(uint4*)&av[r*132 + k4*4] = f2tf4(e4[idx]);
        *(uint4*)&wt[r*132 + k4*4] = f2tf4(w4[idx]);
    }
    __syncthreads();
    const int wid = tid>>5, lane = tid&31, g = lane>>2, t4 = lane&3;
    float acc[16][4];
    #pragma unroll
    for (int nf=0;nf<16;nf++)
        #pragma unroll
        for (int i=0;i<4;i++) acc[nf][i]=0.f;
    #pragma unroll
    for (int ks = 0; ks < 16; ks++) {
        const int k0 = ks*8;
        unsigned af[4];
        int base = (wid*16 + g)*132 + k0 + t4;
        af[0] = av[base]; af[1] = av[base + 8*132];
        af[2] = av[base + 4]; af[3] = av[base + 8*132 + 4];
        #pragma unroll
        for (int nf = 0; nf < 16; nf++) {
            int bb = (nf*8 + g)*132 + k0 + t4;
            unsigned bf[2] = { wt[bb], wt[bb + 4] };
            mma_tf32(acc[nf], af, bf);
        }
    }
    float sA = 0.f, sB = 0.f;
    #pragma unroll
    for (int nf = 0; nf < 16; nf++) {
        sA += acc[nf][0]*acc[nf][0] + acc[nf][1]*acc[nf][1];
        sB += acc[nf][2]*acc[nf][2] + acc[nf][3]*acc[nf][3];
    }
    #pragma unroll
    for (int o = 1; o < 4; o <<= 1) {
        sA += __shfl_xor_sync(~0u, sA, o);
        sB += __shfl_xor_sync(~0u, sB, o);
    }
    float iA = 1.f/fmaxf(sqrtf(sA), 1e-12f);
    float iB = 1.f/fmaxf(sqrtf(sB), 1e-12f);
    int rA = r0 + wid*16 + g, rB = rA + 8;
    #pragma unroll
    for (int nf = 0; nf < 16; nf++) {
        *(float2*)&g_text[rA*NH + nf*8 + t4*2] = make_float2(acc[nf][0]*iA, acc[nf][1]*iA);
        *(float2*)&g_text[rB*NH + nf*8 + t4*2] = make_float2(acc[nf][2]*iB, acc[nf][3]*iB);
    }
}

// ---------------- k_proj: tf32 TC, 512 thr, both projections, compacted outputs ----------------
#define PROJ_SMEM_B (3*128*132*4)
__global__ __launch_bounds__(512) void k_proj(const float* __restrict__ bbox,
                                              const float* __restrict__ Wp,
                                              const float* __restrict__ Wpi) {
    extern __shared__ unsigned su[];
    unsigned* av = su;
    unsigned* wp = su + 128*132;
    unsigned* wi = su + 2*128*132;
    const int m0 = blockIdx.x*128, b = m0 >> 10;
    const int tid = threadIdx.x;
    const float4* a4 = (const float4*)(bbox + m0*NH);
    const float4* p4 = (const float4*)Wp;
    const float4* i4 = (const float4*)Wpi;
    for (int idx = tid; idx < 4096; idx += 512) {
        int r = idx >> 5, k4 = idx & 31;
        *(uint4*)&av[r*132 + k4*4] = f2tf4(a4[idx]);
        *(uint4*)&wp[r*132 + k4*4] = f2tf4(p4[idx]);
        *(uint4*)&wi[r*132 + k4*4] = f2tf4(i4[idx]);
    }
    __syncthreads();
    const int wid = tid>>5, lane = tid&31, g = lane>>2, t4 = lane&3;
    const int wm = wid & 7, wn = wid >> 3;     // wn: 0 -> Wp(boxl), 1 -> Wpi(boxi)
    const unsigned* wb = wn ? wi : wp;
    float acc[16][4];
    #pragma unroll
    for (int nf=0;nf<16;nf++)
        #pragma unroll
        for (int i=0;i<4;i++) acc[nf][i] = 0.f;

    #pragma unroll
    for (int ks = 0; ks < 16; ks++) {
        const int k0 = ks*8;
        unsigned af[4];
        int base = (wm*16 + g)*132 + k0 + t4;
        af[0] = av[base];
        af[1] = av[base + 8*132];
        af[2] = av[base + 4];
        af[3] = av[base + 8*132 + 4];
        #pragma unroll
        for (int nf = 0; nf < 16; nf++) {
            int bb = (nf*8 + g)*132 + k0 + t4;
            unsigned bf[2] = { wb[bb], wb[bb + 4] };
            mma_tf32(acc[nf], af, bf);
        }
    }
    float sA = 0.f, sB = 0.f;
    #pragma unroll
    for (int nf = 0; nf < 16; nf++) {
        sA += acc[nf][0]*acc[nf][0] + acc[nf][1]*acc[nf][1];
        sB += acc[nf][2]*acc[nf][2] + acc[nf][3]*acc[nf][3];
    }
    #pragma unroll
    for (int o = 1; o < 4; o <<= 1) {
        sA += __shfl_xor_sync(~0u, sA, o);
        sB += __shfl_xor_sync(~0u, sB, o);
    }
    float iA = 1.f/fmaxf(sqrtf(sA), 1e-12f);
    float iB = 1.f/fmaxf(sqrtf(sB), 1e-12f);
    #pragma unroll
    for (int nf = 0; nf < 16; nf++) {
        acc[nf][0] *= iA; acc[nf][1] *= iA;
        acc[nf][2] *= iB; acc[nf][3] *= iB;
    }
    const int rA = wm*16 + g, rB = rA + 8;
    #pragma unroll
    for (int rr = 0; rr < 2; rr++) {
        int rloc = rr ? rB : rA;
        int gp = m0 + rloc;
        float mk = g_mask[gp];
        int j = g_pos[gp];
        if (wn == 1) {  // boxi: full fp32 + compacted tf32
            float* dst = g_boxi + gp*NH + t4*2;
            unsigned* cdst = (mk > 0.f) ? (g_boxc + (b*NP + j)*NH + t4*2) : 0;
            #pragma unroll
            for (int nf = 0; nf < 16; nf++) {
                float c0 = acc[nf][rr*2], c1 = acc[nf][rr*2+1];
                *(float2*)(dst + nf*8) = make_float2(c0, c1);
                if (cdst) *(uint2*)(cdst + nf*8) = make_uint2(f2tf(c0), f2tf(c1));
            }
        } else {        // boxl: compacted tf32 only
            if (mk > 0.f) {
                unsigned* cdst = g_boxlc + (b*NP + j)*NH + t4*2;
                #pragma unroll
                for (int nf = 0; nf < 16; nf++)
                    *(uint2*)(cdst + nf*8) =
                        make_uint2(f2tf(acc[nf][rr*2]), f2tf(acc[nf][rr*2+1]));
            }
        }
    }
}

__device__ __forceinline__ int lang_num_at(const int* ln, int b) {
    return (ln[1] == 0) ? ln[2*b] : ln[b];
}

// ---------------- k_lang: tf32 TC over compacted columns ----------------
#define LANG_SMEM ((32*132 + 128*132)*4 + (3*256 + 3*32 + 128)*4)
__global__ __launch_bounds__(512) void k_lang_tc(const int* __restrict__ ln) {
    extern __shared__ unsigned smu[];
    unsigned* at = smu;                   // [32][132] text tf32
    unsigned* bs = smu + 32*132;          // [128][132] boxlc tile
    float* fb  = (float*)(smu + 32*132 + 128*132);
    float* pm  = fb;                      // [8][32]
    float* ps  = pm + 256;                // [8][32]
    float* pt  = ps + 256;                // [8][32]
    float* rmS = pt + 256;                // [32]
    float* rsS = rmS + 32;
    float* rtS = rsS + 32;
    float* ms  = rtS + 32;                // [128]

    const int b = blockIdx.x, tid = threadIdx.x;
    const int cnt = g_cntI[b];
    const int qtiles = (cnt + 127) >> 7;
    const int wid = tid >> 5, lane = tid & 31;
    const int g = lane >> 2, t4 = lane & 3;
    const int wm = wid & 1, wn = wid >> 1;   // 2 m-tiles x 8 col-groups(16 cols)

    const float4* tx4 = (const float4*)(g_text + b*NL*NH);
    for (int idx = tid; idx < 1024; idx += 512) {
        int r = idx >> 5, k4 = idx & 31;
        *(uint4*)&at[r*132 + k4*4] = f2tf4(tx4[idx]);
    }
    if (tid < 32) { rmS[tid] = -1e30f; rsS[tid] = 0.f; rtS[tid] = 0.f; }

    for (int qt = 0; qt < qtiles; qt++) {
        __syncthreads();
        const uint4* Xb = (const uint4*)(g_boxlc + (b*NP + qt*128)*NH);
        for (int idx = tid; idx < 4096; idx += 512) {
            int q = idx >> 5, k4 = idx & 31;
            *(uint4*)&bs[q*132 + k4*4] = Xb[idx];
        }
        if (tid < 128) ms[tid] = (qt*128 + tid < cnt) ? 1.f : 0.f;
        __syncthreads();

        float acc[2][4];
        #pragma unroll
        for (int nf=0;nf<2;nf++)
            #pragma unroll
            for (int i=0;i<4;i++) acc[nf][i] = 0.f;
        #pragma unroll
        for (int ks = 0; ks < 16; ks++) {
            const int k0 = ks*8;
            unsigned af[4];
            int base = (wm*16 + g)*132 + k0 + t4;
            af[0] = at[base];
            af[1] = at[base + 8*132];
            af[2] = at[base + 4];
            af[3] = at[base + 8*132 + 4];
            #pragma unroll
            for (int nf = 0; nf < 2; nf++) {
                int bb = (wn*16 + nf*8 + g)*132 + k0 + t4;
                unsigned bf[2] = { bs[bb], bs[bb + 4] };
                mma_tf32(acc[nf], af, bf);
            }
        }
        const int rA = wm*16 + g, rB = rA + 8;
        float mA = -1e30f, mB = -1e30f, tA = 0.f, tB = 0.f;
        float m0v[2], m1v[2];
        #pragma unroll
        for (int nf = 0; nf < 2; nf++) {
            int col0 = wn*16 + nf*8 + t4*2;
            m0v[nf] = ms[col0]; m1v[nf] = ms[col0 + 1];
            float2 tgA = *(float2*)&g_tgtc[(b*NL + rA)*NP + qt*128 + col0];
            float2 tgB = *(float2*)&g_tgtc[(b*NL + rB)*NP + qt*128 + col0];
            tA += tgA.x*acc[nf][0] + tgA.y*acc[nf][1];
            tB += tgB.x*acc[nf][2] + tgB.y*acc[nf][3];
            mA = fmaxf(mA, (m0v[nf] > 0.f) ? acc[nf][0] : -1e30f);
            mA = fmaxf(mA, (m1v[nf] > 0.f) ? acc[nf][1] : -1e30f);
            mB = fmaxf(mB, (m0v[nf] > 0.f) ? acc[nf][2] : -1e30f);
            mB = fmaxf(mB, (m1v[nf] > 0.f) ? acc[nf][3] : -1e30f);
        }
        #pragma unroll
        for (int o = 1; o < 4; o <<= 1) {
            mA = fmaxf(mA, __shfl_xor_sync(~0u, mA, o));
            mB = fmaxf(mB, __shfl_xor_sync(~0u, mB, o));
        }
        float eA = 0.f, eB = 0.f;
        #pragma unroll
        for (int nf = 0; nf < 2; nf++) {
            eA += (m0v[nf] > 0.f) ? __expf(acc[nf][0] - mA) : 0.f;
            eA += (m1v[nf] > 0.f) ? __expf(acc[nf][1] - mA) : 0.f;
            eB += (m0v[nf] > 0.f) ? __expf(acc[nf][2] - mB) : 0.f;
            eB += (m1v[nf] > 0.f) ? __expf(acc[nf][3] - mB) : 0.f;
        }
        #pragma unroll
        for (int o = 1; o < 4; o <<= 1) {
            eA += __shfl_xor_sync(~0u, eA, o);
            eB += __shfl_xor_sync(~0u, eB, o);
            tA += __shfl_xor_sync(~0u, tA, o);
            tB += __shfl_xor_sync(~0u, tB, o);
        }
        if (t4 == 0) {
            pm[wn*32 + rA] = mA; ps[wn*32 + rA] = eA; pt[wn*32 + rA] = tA;
            pm[wn*32 + rB] = mB; ps[wn*32 + rB] = eB; pt[wn*32 + rB] = tB;
        }
        __syncthreads();
        if (tid < 32) {
            float m = rmS[tid], s = rsS[tid], t = rtS[tid];
            #pragma unroll
            for (int wg = 0; wg < 8; wg++) {
                float om = pm[wg*32 + tid], os = ps[wg*32 + tid];
                float nm = fmaxf(m, om);
                s = ((s > 0.f) ? s*__expf(m - nm) : 0.f)
                  + ((os > 0.f) ? os*__expf(om - nm) : 0.f);
                m = nm;
                t += pt[wg*32 + tid];
            }
            rmS[tid] = m; rsS[tid] = s; rtS[tid] = t;
        }
    }
    __syncthreads();
    if (tid < 32) {
        int l = tid;
        float n = g_nl[b*NL + l];
        float cnt1 = fmaxf(g_cnt[b], 1.f);
        float val = 0.f;
        if (n > 0.f && rsS[l] > 0.f)
            val = 0.5f*(n*(rmS[l] + logf(rsS[l])) - rtS[l])/cnt1;
        bool act = l < lang_num_at(ln, b);
        g_lang[b*NL + l] = act ? val : 0.f;
    }
}

// ---------------- k_iou: compacted tf32 TC GEMM + masked row logsumexp, 512 thr ----------------
#define IOU_TC_SMEM (2*128*132*4 + 128*4 + 2*2*128*4 + 2*128*4)
__global__ __launch_bounds__(512) void k_iou_tc() {
    extern __shared__ unsigned smu[];
    unsigned* as = smu;
    unsigned* bs = smu + 128*132;
    float* ms  = (float*)(smu + 2*128*132);
    float* pm  = ms + 128;
    float* ps  = pm + 256;
    float* rmS = ps + 256;
    float* rsS = rmS + 128;

    const int b = blockIdx.y, r0 = blockIdx.x*128, tid = threadIdx.x;
    const int cnt = g_cntI[b];
    if (r0 >= cnt) return;
    const int qtiles = (cnt + 127) >> 7;
    const int wid = tid >> 5, lane = tid & 31;
    const int g = lane >> 2, t4 = lane & 3;
    const int wm = wid & 7, wn = wid >> 3;
    const uint4* Xa = (const uint4*)(g_boxc + (b*NP + r0)*NH);

    for (int idx = tid; idx < 4096; idx += 512) {
        int r = idx >> 5, k4 = idx & 31;
        *(uint4*)&as[r*132 + k4*4] = Xa[idx];
    }
    if (tid < 128) { rmS[tid] = -1e30f; rsS[tid] = 0.f; }

    for (int qt = 0; qt < qtiles; qt++) {
        __syncthreads();
        const uint4* Xb = (const uint4*)(g_boxc + (b*NP + qt*128)*NH);
        for (int idx = tid; idx < 4096; idx += 512) {
            int q = idx >> 5, k4 = idx & 31;
            *(uint4*)&bs[q*132 + k4*4] = Xb[idx];
        }
        if (tid < 128) ms[tid] = (qt*128 + tid < cnt) ? 1.f : 0.f;
        __syncthreads();

        float acc[8][4];
        #pragma unroll
        for (int nf=0;nf<8;nf++)
            #pragma unroll
            for (int i=0;i<4;i++) acc[nf][i] = 0.f;

        #pragma unroll
        for (int ks = 0; ks < 16; ks++) {
            const int k0 = ks*8;
            unsigned af[4];
            int base = (wm*16 + g)*132 + k0 + t4;
            af[0] = as[base];
            af[1] = as[base + 8*132];
            af[2] = as[base + 4];
            af[3] = as[base + 8*132 + 4];
            #pragma unroll
            for (int nf = 0; nf < 8; nf++) {
                int bb = (wn*64 + nf*8 + g)*132 + k0 + t4;
                unsigned bf[2] = { bs[bb], bs[bb + 4] };
                mma_tf32(acc[nf], af, bf);
            }
        }
        float cm0[8], cm1[8];
        #pragma unroll
        for (int nf = 0; nf < 8; nf++) {
            cm0[nf] = ms[wn*64 + nf*8 + t4*2];
            cm1[nf] = ms[wn*64 + nf*8 + t4*2 + 1];
        }
        {
            const int rA = wm*16 + g, rB = rA + 8;
            float mA = -1e30f, mB = -1e30f;
            #pragma unroll
            for (int nf = 0; nf < 8; nf++) {
                mA = fmaxf(mA, (cm0[nf] > 0.f) ? acc[nf][0] : -1e30f);
                mA = fmaxf(mA, (cm1[nf] > 0.f) ? acc[nf][1] : -1e30f);
                mB = fmaxf(mB, (cm0[nf] > 0.f) ? acc[nf][2] : -1e30f);
                mB = fmaxf(mB, (cm1[nf] > 0.f) ? acc[nf][3] : -1e30f);
            }
            #pragma unroll
            for (int o = 1; o < 4; o <<= 1) {
                mA = fmaxf(mA, __shfl_xor_sync(~0u, mA, o));
                mB = fmaxf(mB, __shfl_xor_sync(~0u, mB, o));
            }
            float eA = 0.f, eB = 0.f;
            #pragma unroll
            for (int nf = 0; nf < 8; nf++) {
                eA += (cm0[nf] > 0.f) ? __expf(acc[nf][0] - mA) : 0.f;
                eA += (cm1[nf] > 0.f) ? __expf(acc[nf][1] - mA) : 0.f;
                eB += (cm0[nf] > 0.f) ? __expf(acc[nf][2] - mB) : 0.f;
                eB += (cm1[nf] > 0.f) ? __expf(acc[nf][3] - mB) : 0.f;
            }
            #pragma unroll
            for (int o = 1; o < 4; o <<= 1) {
                eA += __shfl_xor_sync(~0u, eA, o);
                eB += __shfl_xor_sync(~0u, eB, o);
            }
            if (t4 == 0) {
                pm[wn*128 + rA] = mA; ps[wn*128 + rA] = eA;
                pm[wn*128 + rB] = mB; ps[wn*128 + rB] = eB;
            }
        }
        __syncthreads();
        if (tid < 128) {
            float m0 = pm[tid], s0 = ps[tid], m1 = pm[128+tid], s1 = ps[128+tid];
            float tm = fmaxf(m0, m1);
            float te = ((s0 > 0.f) ? s0*__expf(m0 - tm) : 0.f)
                     + ((s1 > 0.f) ? s1*__expf(m1 - tm) : 0.f);
            float rm = rmS[tid], nm = fmaxf(rm, tm);
            float rs = rsS[tid];
            rs = ((rs > 0.f) ? rs*__expf(rm - nm) : 0.f)
               + ((te > 0.f) ? te*__expf(tm - nm) : 0.f);
            rmS[tid] = nm; rsS[tid] = rs;
        }
    }
    __syncthreads();
    if (tid < 128) {
        int r = r0 + tid;
        if (r < cnt) {
            float lse = (rsS[tid] > 0.f) ? rmS[tid] + logf(rsS[tid]) : 0.f;
            g_lse[b*NP + g_idx[b*NP + r]] = lse;
        }
    }
}

// ---------------- k_vsum: list-gather, exact fp32 ----------------
__global__ void k_vsum(const int* __restrict__ ln) {
    int l = blockIdx.x, b = blockIdx.y, h = threadIdx.x;  // 128
    int nn = g_nli[b*NL+l];
    const int* plist = g_plist + (b*NL+l)*NP;
    float v = 0.f;
    for (int j = 0; j < nn; j++) {
        int p = __ldg(&plist[j]);
        v += g_boxi[(b*NP + p)*NH + h];
    }
    float lsum = 0.f;
    for (int j = h; j < nn; j += 128)
        lsum += g_lse[b*NP + __ldg(&plist[j])];
    float vv = v*v;
    for (int o = 16; o; o >>= 1) {
        vv   += __shfl_xor_sync(~0u, vv, o);
        lsum += __shfl_xor_sync(~0u, lsum, o);
    }
    __shared__ float redv[4], redl[4];
    if ((h&31)==0) { redv[h>>5] = vv; redl[h>>5] = lsum; }
    __syncthreads();
    if (h == 0) {
        vv   = redv[0]+redv[1]+redv[2]+redv[3];
        lsum = redl[0]+redl[1]+redl[2]+redl[3];
        float n = g_nl[b*NL+l];
        float cnt1 = fmaxf(g_cnt[b], 1.f);
        float val = 0.f;
        if (n > 0.f) val = (n*lsum - vv)/(cnt1*cnt1);
        bool act = l < lang_num_at(ln, b);
        g_iou[b*NL+l] = act ? val : 0.f;
    }
}

__global__ void k_final(float* __restrict__ out) {
    int tid = threadIdx.x;  // 1024
    float a = g_lang[tid], c = g_iou[tid];
    for (int o = 16; o; o >>= 1) {
        a += __shfl_xor_sync(~0u, a, o);
        c += __shfl_xor_sync(~0u, c, o);
    }
    __shared__ float ra[32], rc[32];
    if ((tid&31)==0) { ra[tid>>5]=a; rc[tid>>5]=c; }
    __syncthreads();
    if (tid < 32) {
        a = ra[tid]; c = rc[tid];
        for (int o = 16; o; o >>= 1) {
            a += __shfl_xor_sync(~0u, a, o);
            c += __shfl_xor_sync(~0u, c, o);
        }
        if (tid == 0) { out[0] = a/(float)NB; out[1] = c/(float)NB; }
    }
}

extern "C" void kernel_launch(void* const* d_in, const int* in_sizes, int n_in,
                              void* d_out, int out_size) {
    const float* pred_center = (const float*)d_in[0];
    const float* pred_size   = (const float*)d_in[1];
    const float* bbox        = (const float*)d_in[2];
    const float* gt_center   = (const float*)d_in[3];
    const float* gt_size     = (const float*)d_in[4];
    const float* lang_emb    = (const float*)d_in[5];
    const float* obj         = (const float*)d_in[6];
    const float* Wt          = (const float*)d_in[7];
    const float* Wp          = (const float*)d_in[8];
    const float* Wpi         = (const float*)d_in[9];
    const int*   lang_num    = (const int*)d_in[10];
    float* out = (float*)d_out;

    static bool attr_done = false;
    if (!attr_done) {
        cudaFuncSetAttribute(k_proj, cudaFuncAttributeMaxDynamicSharedMemorySize,
                             PROJ_SMEM_B);
        cudaFuncSetAttribute(k_iou_tc, cudaFuncAttributeMaxDynamicSharedMemorySize,
                             IOU_TC_SMEM);
        cudaFuncSetAttribute(k_text_tc, cudaFuncAttributeMaxDynamicSharedMemorySize,
                             TEXT_SMEM);
        cudaFuncSetAttribute(k_lang_tc, cudaFuncAttributeMaxDynamicSharedMemorySize,
                             LANG_SMEM);
        attr_done = true;
    }

    k_maskscan<<<NB, 1024>>>(obj);
    k_tgt<<<dim3(NL, NB), 256>>>(pred_center, pred_size, gt_center, gt_size);
    k_text_tc<<<(NB*NL)/128, 256, TEXT_SMEM>>>(lang_emb, Wt);
    k_proj<<<(NB*NP)/128, 512, PROJ_SMEM_B>>>(bbox, Wp, Wpi);
    k_iou_tc<<<dim3(NP/128, NB), 512, IOU_TC_SMEM>>>();
    k_lang_tc<<<NB, 512, LANG_SMEM>>>(lang_num);
    k_vsum<<<dim3(NL, NB), 128>>>(lang_num);
    k_final<<<1, 1024>>>(out);
}